// round 5
// baseline (speedup 1.0000x reference)
#include <cuda_runtime.h>
#include <cstdint>

// Haar (db1) 2-D DWT on (B=16, C=3, H=1024, W=1024) fp32.
// Output: concatenated planes [cA | cH | cV | cD], each (16,3,512,512).
//
// R3: one thread handles a 4-row x 8-col input tile (= 2 output rows x 4 cols):
//   8 front-batched __ldcs float4 loads (MLP=8), 2 default-policy float4
//   stores per plane (writes linger in L2; dead reads marked evict-first).

static constexpr int Bc    = 16 * 3;        // images
static constexpr int H     = 1024;
static constexpr int W     = 1024;
static constexpr int H2    = H / 2;         // 512
static constexpr int H4    = H / 4;         // 4-row tiles = 256
static constexpr int W2    = W / 2;         // 512
static constexpr int W8    = W / 8;         // 8-col tiles per row = 128
static constexpr int PLANE = Bc * H2 * W2;  // elements per output plane

__global__ __launch_bounds__(256)
void haar_dwt_kernel(const float* __restrict__ x, float* __restrict__ out) {
    int t = blockIdx.x * blockDim.x + threadIdx.x;
    // t in [0, Bc*H4*W8)
    int j  = t & (W8 - 1);          // 8-col tile index
    int r  = t >> 7;                // / W8
    int i  = r & (H4 - 1);          // 4-row tile index
    int bc = r >> 8;                // / H4

    const float4* base = reinterpret_cast<const float4*>(
        x + (size_t)bc * H * W + (size_t)(4 * i) * W) + 2 * j;
    const int RS = W / 4;           // row stride in float4

    // 8 front-batched streaming loads (rows 4i..4i+3, cols 8j..8j+7)
    float4 a0 = __ldcs(base);            float4 a1 = __ldcs(base + 1);
    float4 b0 = __ldcs(base + RS);       float4 b1 = __ldcs(base + RS + 1);
    float4 c0 = __ldcs(base + 2 * RS);   float4 c1 = __ldcs(base + 2 * RS + 1);
    float4 d0 = __ldcs(base + 3 * RS);   float4 d1 = __ldcs(base + 3 * RS + 1);

    // ---- output row 2i (input rows 4i, 4i+1) ----
    float s0 = a0.x + a0.y, e0 = a0.x - a0.y;
    float s1 = b0.x + b0.y, e1 = b0.x - b0.y;
    float s2 = a0.z + a0.w, e2 = a0.z - a0.w;
    float s3 = b0.z + b0.w, e3 = b0.z - b0.w;
    float s4 = a1.x + a1.y, e4 = a1.x - a1.y;
    float s5 = b1.x + b1.y, e5 = b1.x - b1.y;
    float s6 = a1.z + a1.w, e6 = a1.z - a1.w;
    float s7 = b1.z + b1.w, e7 = b1.z - b1.w;

    float4 cA0 = make_float4((s0 + s1) * 0.5f, (s2 + s3) * 0.5f,
                             (s4 + s5) * 0.5f, (s6 + s7) * 0.5f);
    float4 cH0 = make_float4((s0 - s1) * 0.5f, (s2 - s3) * 0.5f,
                             (s4 - s5) * 0.5f, (s6 - s7) * 0.5f);
    float4 cV0 = make_float4((e0 + e1) * 0.5f, (e2 + e3) * 0.5f,
                             (e4 + e5) * 0.5f, (e6 + e7) * 0.5f);
    float4 cD0 = make_float4((e0 - e1) * 0.5f, (e2 - e3) * 0.5f,
                             (e4 - e5) * 0.5f, (e6 - e7) * 0.5f);

    // ---- output row 2i+1 (input rows 4i+2, 4i+3) ----
    float u0 = c0.x + c0.y, f0 = c0.x - c0.y;
    float u1 = d0.x + d0.y, f1 = d0.x - d0.y;
    float u2 = c0.z + c0.w, f2 = c0.z - c0.w;
    float u3 = d0.z + d0.w, f3 = d0.z - d0.w;
    float u4 = c1.x + c1.y, f4 = c1.x - c1.y;
    float u5 = d1.x + d1.y, f5 = d1.x - d1.y;
    float u6 = c1.z + c1.w, f6 = c1.z - c1.w;
    float u7 = d1.z + d1.w, f7 = d1.z - d1.w;

    float4 cA1 = make_float4((u0 + u1) * 0.5f, (u2 + u3) * 0.5f,
                             (u4 + u5) * 0.5f, (u6 + u7) * 0.5f);
    float4 cH1 = make_float4((u0 - u1) * 0.5f, (u2 - u3) * 0.5f,
                             (u4 - u5) * 0.5f, (u6 - u7) * 0.5f);
    float4 cV1 = make_float4((f0 + f1) * 0.5f, (f2 + f3) * 0.5f,
                             (f4 + f5) * 0.5f, (f6 + f7) * 0.5f);
    float4 cD1 = make_float4((f0 - f1) * 0.5f, (f2 - f3) * 0.5f,
                             (f4 - f5) * 0.5f, (f6 - f7) * 0.5f);

    size_t o0 = (size_t)bc * H2 * W2 + (size_t)(2 * i) * W2 + 4 * j;  // 16B aligned
    size_t o1 = o0 + W2;                                              // next output row

    float4* pA = reinterpret_cast<float4*>(out + o0);
    float4* pH = reinterpret_cast<float4*>(out + PLANE + o0);
    float4* pV = reinterpret_cast<float4*>(out + 2 * (size_t)PLANE + o0);
    float4* pD = reinterpret_cast<float4*>(out + 3 * (size_t)PLANE + o0);
    *pA = cA0; *pH = cH0; *pV = cV0; *pD = cD0;

    pA = reinterpret_cast<float4*>(out + o1);
    pH = reinterpret_cast<float4*>(out + PLANE + o1);
    pV = reinterpret_cast<float4*>(out + 2 * (size_t)PLANE + o1);
    pD = reinterpret_cast<float4*>(out + 3 * (size_t)PLANE + o1);
    *pA = cA1; *pH = cH1; *pV = cV1; *pD = cD1;
}

extern "C" void kernel_launch(void* const* d_in, const int* in_sizes, int n_in,
                              void* d_out, int out_size) {
    const float* x  = (const float*)d_in[0];
    float* out      = (float*)d_out;

    int total_threads = Bc * H4 * W8;          // 1,572,864
    int block = 256;
    int grid  = total_threads / block;         // 6144
    haar_dwt_kernel<<<grid, block>>>(x, out);
}

// round 7
// speedup vs baseline: 1.0211x; 1.0211x over previous
#include <cuda_runtime.h>
#include <cstdint>

// Haar (db1) 2-D DWT on (B=16, C=3, H=1024, W=1024) fp32.
// Output: concatenated planes [cA | cH | cV | cD], each (16,3,512,512).
//
// R6: best-measured tile (R2: 2 rows x 8 cols per thread, MLP=4, 32 regs),
// isolating the store-policy variable: __ldcs loads (dead data, evict-first)
// + DEFAULT-policy stores (dirty lines linger in 126MB L2, writebacks drain
// in larger batched bursts -> fewer DRAM bus turnarounds).

static constexpr int Bc    = 16 * 3;        // images
static constexpr int H     = 1024;
static constexpr int W     = 1024;
static constexpr int H2    = H / 2;         // 512
static constexpr int W2    = W / 2;         // 512
static constexpr int W8    = W / 8;         // 8-col tiles per row = 128
static constexpr int PLANE = Bc * H2 * W2;  // elements per output plane

__global__ __launch_bounds__(256, 8)
void haar_dwt_kernel(const float* __restrict__ x, float* __restrict__ out) {
    int t = blockIdx.x * blockDim.x + threadIdx.x;
    // t in [0, Bc*H2*W8)
    int j  = t & (W8 - 1);          // 8-col tile index
    int r  = t >> 7;                // / W8
    int i  = r & (H2 - 1);          // output row
    int bc = r >> 9;                // / H2

    const float4* row0 = reinterpret_cast<const float4*>(
        x + (size_t)bc * H * W + (size_t)(2 * i) * W) + 2 * j;
    const float4* row1 = row0 + (W / 4);

    // front-batch all 4 loads (MLP=4), streaming/evict-first (no reuse)
    float4 a0 = __ldcs(row0);
    float4 a1 = __ldcs(row0 + 1);
    float4 b0 = __ldcs(row1);
    float4 b1 = __ldcs(row1 + 1);

    float s0 = a0.x + a0.y, d0 = a0.x - a0.y;
    float s1 = b0.x + b0.y, d1 = b0.x - b0.y;
    float s2 = a0.z + a0.w, d2 = a0.z - a0.w;
    float s3 = b0.z + b0.w, d3 = b0.z - b0.w;
    float s4 = a1.x + a1.y, d4 = a1.x - a1.y;
    float s5 = b1.x + b1.y, d5 = b1.x - b1.y;
    float s6 = a1.z + a1.w, d6 = a1.z - a1.w;
    float s7 = b1.z + b1.w, d7 = b1.z - b1.w;

    float4 cA = make_float4((s0 + s1) * 0.5f, (s2 + s3) * 0.5f,
                            (s4 + s5) * 0.5f, (s6 + s7) * 0.5f);
    float4 cH = make_float4((s0 - s1) * 0.5f, (s2 - s3) * 0.5f,
                            (s4 - s5) * 0.5f, (s6 - s7) * 0.5f);
    float4 cV = make_float4((d0 + d1) * 0.5f, (d2 + d3) * 0.5f,
                            (d4 + d5) * 0.5f, (d6 + d7) * 0.5f);
    float4 cD = make_float4((d0 - d1) * 0.5f, (d2 - d3) * 0.5f,
                            (d4 - d5) * 0.5f, (d6 - d7) * 0.5f);

    size_t o = (size_t)bc * H2 * W2 + (size_t)i * W2 + 4 * j;  // 16B aligned
    // default-policy stores: allow L2 write-lingering / batched writeback
    *reinterpret_cast<float4*>(out + o)                     = cA;
    *reinterpret_cast<float4*>(out + PLANE + o)             = cH;
    *reinterpret_cast<float4*>(out + 2 * (size_t)PLANE + o) = cV;
    *reinterpret_cast<float4*>(out + 3 * (size_t)PLANE + o) = cD;
}

extern "C" void kernel_launch(void* const* d_in, const int* in_sizes, int n_in,
                              void* d_out, int out_size) {
    const float* x  = (const float*)d_in[0];
    float* out      = (float*)d_out;

    int total_threads = Bc * H2 * W8;          // 3,145,728
    int block = 256;
    int grid  = total_threads / block;         // 12288
    haar_dwt_kernel<<<grid, block>>>(x, out);
}